// round 10
// baseline (speedup 1.0000x reference)
#include <cuda_runtime.h>
#include <cuda_fp16.h>
#include <cstdint>

// ===========================================================================
// CFConv via mma.sync (HMMA fp16 m16n8k16, fp32 accum), single-pass fp16.
// 256 thr / CTA = 8 warps = 2 atom-quads; 8 atoms per CTA (4 tiles).
// x-gather prefetched via cp.async into smem (lane = neighbor row, no
// shuffles), hidden behind GEMM1+softplus+GEMM2. 112 KB smem -> 2 CTAs/SM.
// ===========================================================================

#define N_THREADS 256
#define ATOMS_PER_CTA 8
#define F_DIM 128

// padded element strides (odd multiples of 8 halves -> conflict-free ldmatrix)
#define S1 72    // K=64 tiles
#define S2 136   // K=128 tiles
#define XR 132   // xs row stride in floats (132*4=528 B)

// ---- smem byte offsets ----
#define SM_B1H 0                         // 128*72*2  = 18432
#define SM_B2H (SM_B1H + 128*S1*2)       // 128*136*2 = 34816 -> ends 53248
#define SM_A1H (SM_B2H + 128*S2*2)       // 64*72*2   = 9216  -> ends 62464
#define SM_HH  (SM_A1H + 64*S1*2)        // 64*136*2  = 17408 -> ends 79872
#define SM_XS  (SM_HH  + 64*S2*2)        // 2 * 32*XR*4 = 33792 -> ends 113664
#define SM_BS1 (SM_XS  + 2*32*XR*4)      // 512
#define SM_BS2 (SM_BS1 + 512)
#define SMEM_BYTES (SM_BS2 + 512)        // 114688 (2 CTAs: 229376 <= 233472)
#define XS_ATOM (32*XR*4)                // 16896 B per atom slot

#define WIMG_BYTES (128*S1*2 + 128*S2*2) // 53248
__device__ __align__(16) unsigned char g_wimg[WIMG_BYTES];
__device__ int g_idx64_flag;

// ---------------------------------------------------------------------------
__device__ __forceinline__ uint32_t smem_u32(const void* p) {
    uint32_t a;
    asm("{ .reg .u64 t; cvta.to.shared.u64 t, %1; cvt.u32.u64 %0, t; }" : "=r"(a) : "l"(p));
    return a;
}
__device__ __forceinline__ void bar_quad(int id) {
    asm volatile("bar.sync %0, %1;" :: "r"(id), "r"(128) : "memory");
}
__device__ __forceinline__ void ldsm4(uint32_t addr, uint32_t r[4]) {
    asm volatile("ldmatrix.sync.aligned.m8n8.x4.shared.b16 {%0,%1,%2,%3}, [%4];"
        : "=r"(r[0]), "=r"(r[1]), "=r"(r[2]), "=r"(r[3]) : "r"(addr));
}
__device__ __forceinline__ void mma16816(float c[4], const uint32_t a[4],
                                         uint32_t b0, uint32_t b1) {
    asm volatile("mma.sync.aligned.m16n8k16.row.col.f32.f16.f16.f32 "
        "{%0,%1,%2,%3}, {%4,%5,%6,%7}, {%8,%9}, {%0,%1,%2,%3};"
        : "+f"(c[0]), "+f"(c[1]), "+f"(c[2]), "+f"(c[3])
        : "r"(a[0]), "r"(a[1]), "r"(a[2]), "r"(a[3]), "r"(b0), "r"(b1));
}
__device__ __forceinline__ float softplus_fast(float z) {
    return fmaxf(z, 0.0f) + __logf(1.0f + __expf(-fabsf(z)));
}
__device__ __forceinline__ uint32_t pack_h2(float a, float b) {
    __half2 h = __floats2half2_rn(a, b);
    return *reinterpret_cast<uint32_t*>(&h);
}

// A: [64 rows][STRIDE k] fp16; B: [128 n][STRIDE k] fp16. Single pass.
template<int KSTEPS, int STRIDE>
__device__ __forceinline__ void gemm_block(
    uint32_t aH, uint32_t bH,
    int m0, int nb0, int lane, float c[2][4][4])
{
    const uint32_t a_row = m0 + (lane & 15);
    const uint32_t a_k   = (lane >> 4) << 3;
    const uint32_t b_row = nb0 + ((lane >> 4) << 3) + (lane & 7);
    const uint32_t b_k   = ((lane >> 3) & 1) << 3;
    #pragma unroll
    for (int ks = 0; ks < KSTEPS; ++ks) {
        const uint32_t k0 = ks * 16;
        uint32_t ah[2][4];
        #pragma unroll
        for (int mi = 0; mi < 2; ++mi) {
            uint32_t off = ((a_row + mi * 16) * STRIDE + k0 + a_k) * 2;
            ldsm4(aH + off, ah[mi]);
        }
        #pragma unroll
        for (int ng = 0; ng < 2; ++ng) {
            uint32_t boff = ((b_row + ng * 16) * STRIDE + k0 + b_k) * 2;
            uint32_t bh[4];
            ldsm4(bH + boff, bh);
            #pragma unroll
            for (int mi = 0; mi < 2; ++mi)
                #pragma unroll
                for (int nj = 0; nj < 2; ++nj)
                    mma16816(c[mi][ng * 2 + nj], ah[mi], bh[2*nj], bh[2*nj+1]);
        }
    }
}

// ---------------------------------------------------------------------------
// prep: weight transpose + fp16 images; block 0 detects neighbors dtype
// ---------------------------------------------------------------------------
__global__ void prep_weights(const float* __restrict__ w1,
                             const float* __restrict__ w2,
                             const int*   __restrict__ nb_raw) {
    if (blockIdx.x == 0) {
        __shared__ int nonzero;
        if (threadIdx.x == 0) nonzero = 0;
        __syncthreads();
        int local = 0;
        for (int i = threadIdx.x; i < 1024; i += blockDim.x) local |= nb_raw[2 * i + 1];
        if (local) atomicOr(&nonzero, 1);
        __syncthreads();
        if (threadIdx.x == 0) g_idx64_flag = (nonzero == 0) ? 1 : 0;
    }
    uint16_t* b1h = (uint16_t*)(g_wimg);
    uint16_t* b2h = (uint16_t*)(g_wimg + 128*S1*2);
    int stride = gridDim.x * blockDim.x;
    for (int idx = blockIdx.x * blockDim.x + threadIdx.x; idx < 64*128; idx += stride) {
        int r = idx >> 7, f = idx & 127;
        b1h[f * S1 + r] = __half_as_ushort(__float2half_rn(w1[idx]));
    }
    for (int idx = blockIdx.x * blockDim.x + threadIdx.x; idx < 128*128; idx += stride) {
        int g = idx >> 7, f = idx & 127;
        b2h[f * S2 + g] = __half_as_ushort(__float2half_rn(w2[idx]));
    }
}

// ---------------------------------------------------------------------------
__global__ __launch_bounds__(N_THREADS, 2)
void cfconv_mma(const float* __restrict__ x,
                const float* __restrict__ rbf,
                const void*  __restrict__ nbr,
                const float* __restrict__ b1,
                const float* __restrict__ b2,
                float* __restrict__ out,
                int n_atoms)
{
    extern __shared__ __align__(16) char smem[];
    const uint32_t sb = smem_u32(smem);
    const int t = threadIdx.x, wid = t >> 5, lane = t & 31;

    // weights image -> smem: 53248 B = 3328 float4 = 13 x 256
    {
        const float4* src = (const float4*)g_wimg;
        float4* dst = (float4*)smem;
        #pragma unroll
        for (int i = 0; i < 13; ++i) dst[t + i * N_THREADS] = src[t + i * N_THREADS];
    }
    if (t < F_DIM) {
        ((float*)(smem + SM_BS1))[t] = b1[t];
        ((float*)(smem + SM_BS2))[t] = b2[t];
    }
    __syncthreads();   // only CTA-wide sync; weights/biases immutable after

    const int idxsh = g_idx64_flag;
    const int* nb32 = (const int*)nbr;
    const float* bs1 = (const float*)(smem + SM_BS1);
    const float* bs2 = (const float*)(smem + SM_BS2);

    // quad = consecutive warps {4p..4p+3} -> spans all 4 SMSPs.
    const int pair = wid >> 2;          // atom slot within tile (0..1)
    const int sub  = wid & 3;           // N-quarter (0..3)
    const int bid  = pair + 1;          // named barrier id (1..2), 128 thr
    const int m0   = pair * 32;
    const int nb0  = sub * 32;
    const int qt   = sub * 32 + lane;   // thread index within quad (0..127)
    const int qr   = lane >> 2;
    const int qc   = (lane & 3) * 2;

    #pragma unroll 1
    for (int tile = 0; tile < ATOMS_PER_CTA / 2; ++tile) {
        const int abase = blockIdx.x * ATOMS_PER_CTA + tile * 2;
        const int atom  = abase + pair;
        const bool ok = (atom < n_atoms);

        // ---- neighbor index (lane = nb slot) + cp.async x-row prefetch ----
        int j = 0;
        if (ok) j = nb32[((size_t)atom * 32 + lane) << idxsh];
        {
            const char* gsrc = (const char*)(x + (size_t)j * F_DIM + nb0);
            uint32_t sdst = sb + SM_XS + (uint32_t)pair * XS_ATOM
                            + (uint32_t)lane * (XR * 4) + (uint32_t)nb0 * 4;
            #pragma unroll
            for (int i = 0; i < 8; ++i)
                asm volatile("cp.async.cg.shared.global [%0], [%1], 16;"
                             :: "r"(sdst + i * 16), "l"(gsrc + i * 16) : "memory");
            asm volatile("cp.async.commit_group;" ::: "memory");
        }

        // ---- quad stages its atom's rbf rows [32 x 64] -> fp16 ----
        {
            const float4* rg = (const float4*)rbf + (size_t)atom * 512;
            #pragma unroll
            for (int i = 0; i < 4; ++i) {
                int idx = qt + i * 128;                // 0..511
                int row = idx >> 4, c4 = (idx & 15) << 2;
                float4 v = make_float4(0.f, 0.f, 0.f, 0.f);
                if (ok) v = rg[idx];
                uint32_t o = (uint32_t)((m0 + row) * S1 + c4) * 2;
                *(uint2*)(smem + SM_A1H + o) =
                    make_uint2(pack_h2(v.x, v.y), pack_h2(v.z, v.w));
            }
        }
        bar_quad(bid);   // #1: A rows ready (also: quad epilogue done -> HH writable)

        float c[2][4][4];
        #pragma unroll
        for (int mi = 0; mi < 2; ++mi)
            #pragma unroll
            for (int ng = 0; ng < 4; ++ng)
                c[mi][ng][0] = c[mi][ng][1] = c[mi][ng][2] = c[mi][ng][3] = 0.f;

        // ---- GEMM1: A@B1 (fp16) ----
        gemm_block<4, S1>(sb + SM_A1H, sb + SM_B1H, m0, nb0, lane, c);

        // ---- softplus(D1 + b1) -> H rows m0.. (own 32-col quarter) ----
        #pragma unroll
        for (int mi = 0; mi < 2; ++mi) {
            #pragma unroll
            for (int ng = 0; ng < 4; ++ng) {
                const int cc = nb0 + ng * 8 + qc;
                const int r0 = m0 + mi * 16 + qr;
                float s0 = softplus_fast(c[mi][ng][0] + bs1[cc]);
                float s1 = softplus_fast(c[mi][ng][1] + bs1[cc + 1]);
                float s2 = softplus_fast(c[mi][ng][2] + bs1[cc]);
                float s3 = softplus_fast(c[mi][ng][3] + bs1[cc + 1]);
                *(uint32_t*)(smem + SM_HH + (uint32_t)(r0 * S2 + cc) * 2)
                    = pack_h2(s0, s1);
                *(uint32_t*)(smem + SM_HH + (uint32_t)((r0 + 8) * S2 + cc) * 2)
                    = pack_h2(s2, s3);
            }
        }
        bar_quad(bid);   // #2: all 4 col-quarters of H rows m0.. ready

        #pragma unroll
        for (int mi = 0; mi < 2; ++mi)
            #pragma unroll
            for (int ng = 0; ng < 4; ++ng)
                c[mi][ng][0] = c[mi][ng][1] = c[mi][ng][2] = c[mi][ng][3] = 0.f;

        // ---- GEMM2: H@B2 (fp16) ----
        gemm_block<8, S2>(sb + SM_HH, sb + SM_B2H, m0, nb0, lane, c);
        bar_quad(bid);   // #3: quad GEMM2 done -> atom's H rows reusable as wb

        // ---- epilogue: wb = half(D2+b2); reduce against prefetched xs ----
        {
            // per-warp fp16 scratch in the atom's dead H rows (2176 B each)
            uint32_t* wb = (uint32_t*)(smem + SM_HH + (uint32_t)m0 * S2 * 2
                                       + (uint32_t)sub * 2176);
            #pragma unroll
            for (int mi = 0; mi < 2; ++mi) {
                #pragma unroll
                for (int ng = 0; ng < 4; ++ng) {
                    const int cc = nb0 + ng * 8 + qc;     // global col
                    const int lw = ng * 4 + (lane & 3);   // half2 slot 0..15
                    const int r0 = mi * 16 + qr;          // local nb row
                    wb[r0 * 17 + lw] =
                        pack_h2(c[mi][ng][0] + bs2[cc], c[mi][ng][1] + bs2[cc + 1]);
                    wb[(r0 + 8) * 17 + lw] =
                        pack_h2(c[mi][ng][2] + bs2[cc], c[mi][ng][3] + bs2[cc + 1]);
                }
            }
            asm volatile("cp.async.wait_group 0;" ::: "memory");
            __syncwarp();

            const __half* wbh = (const __half*)wb;
            const float* xsr = (const float*)(smem + SM_XS + (uint32_t)pair * XS_ATOM)
                               + nb0 + lane;
            float acc0 = 0.f, acc1 = 0.f;
            #pragma unroll
            for (int nb = 0; nb < 32; nb += 2) {
                acc0 = fmaf(xsr[nb * XR],
                            __half2float(wbh[nb * 34 + lane]), acc0);
                acc1 = fmaf(xsr[(nb + 1) * XR],
                            __half2float(wbh[(nb + 1) * 34 + lane]), acc1);
            }
            if (ok)
                out[(size_t)atom * F_DIM + nb0 + lane] = acc0 + acc1;
        }
        // no barrier here: next-iter bar #1 (same quad) protects A rows, wb, xs.
    }
}

// ---------------------------------------------------------------------------
extern "C" void kernel_launch(void* const* d_in, const int* in_sizes, int n_in,
                              void* d_out, int out_size)
{
    const float* x    = (const float*)d_in[0];
    const float* rbf  = (const float*)d_in[1];
    const void*  nbrs = d_in[2];
    const float* w1   = (const float*)d_in[3];
    const float* b1   = (const float*)d_in[4];
    const float* w2   = (const float*)d_in[5];
    const float* b2   = (const float*)d_in[6];
    float* out = (float*)d_out;

    const int n_atoms = in_sizes[0] / F_DIM;

    cudaFuncSetAttribute(cfconv_mma,
                         cudaFuncAttributeMaxDynamicSharedMemorySize, SMEM_BYTES);

    prep_weights<<<64, 256>>>(w1, w2, (const int*)nbrs);

    const int grid = (n_atoms + ATOMS_PER_CTA - 1) / ATOMS_PER_CTA;
    cfconv_mma<<<grid, N_THREADS, SMEM_BYTES>>>(x, rbf, nbrs, b1, b2, out, n_atoms);
}

// round 11
// speedup vs baseline: 1.1262x; 1.1262x over previous
#include <cuda_runtime.h>
#include <cuda_fp16.h>
#include <cstdint>

// ===========================================================================
// CFConv via mma.sync (HMMA fp16 m16n8k16, fp32 accum), single-pass fp16.
// 256 thr / CTA = 8 warps = 2 atom-quads, quads span all 4 SMSPs.
// Pipeline: 2 named barriers per tile; next-tile A staged under GEMM2;
// x-gather stays on L1-cached __ldg path with 4-wide MLP.
// ===========================================================================

#define N_THREADS 256
#define ATOMS_PER_CTA 4
#define F_DIM 128

// padded element strides (odd multiples of 8 halves -> conflict-free ldmatrix)
#define S1 72    // K=64 tiles
#define S2 136   // K=128 tiles

// ---- smem byte offsets ----
#define SM_B1H 0                         // 128*72*2  = 18432
#define SM_B2H (SM_B1H + 128*S1*2)       // 128*136*2 = 34816 -> ends 53248
#define SM_A1H (SM_B2H + 128*S2*2)       // 64*72*2   = 9216  -> ends 62464
#define SM_HH  (SM_A1H + 64*S1*2)        // 64*136*2  = 17408 -> ends 79872
#define SM_WB  (SM_HH  + 64*S2*2)        // 2*4*2176  = 17408 -> ends 97280
#define SM_BS1 (SM_WB  + 17408)          // 512
#define SM_BS2 (SM_BS1 + 512)
#define SMEM_BYTES (SM_BS2 + 512)        // 98304 (2 CTAs: 196608)

#define WIMG_BYTES (128*S1*2 + 128*S2*2) // 53248
__device__ __align__(16) unsigned char g_wimg[WIMG_BYTES];
__device__ int g_idx64_flag;

// ---------------------------------------------------------------------------
__device__ __forceinline__ uint32_t smem_u32(const void* p) {
    uint32_t a;
    asm("{ .reg .u64 t; cvta.to.shared.u64 t, %1; cvt.u32.u64 %0, t; }" : "=r"(a) : "l"(p));
    return a;
}
__device__ __forceinline__ void bar_quad(int id) {
    asm volatile("bar.sync %0, %1;" :: "r"(id), "r"(128) : "memory");
}
__device__ __forceinline__ void ldsm4(uint32_t addr, uint32_t r[4]) {
    asm volatile("ldmatrix.sync.aligned.m8n8.x4.shared.b16 {%0,%1,%2,%3}, [%4];"
        : "=r"(r[0]), "=r"(r[1]), "=r"(r[2]), "=r"(r[3]) : "r"(addr));
}
__device__ __forceinline__ void mma16816(float c[4], const uint32_t a[4],
                                         uint32_t b0, uint32_t b1) {
    asm volatile("mma.sync.aligned.m16n8k16.row.col.f32.f16.f16.f32 "
        "{%0,%1,%2,%3}, {%4,%5,%6,%7}, {%8,%9}, {%0,%1,%2,%3};"
        : "+f"(c[0]), "+f"(c[1]), "+f"(c[2]), "+f"(c[3])
        : "r"(a[0]), "r"(a[1]), "r"(a[2]), "r"(a[3]), "r"(b0), "r"(b1));
}
__device__ __forceinline__ float softplus_fast(float z) {
    return fmaxf(z, 0.0f) + __logf(1.0f + __expf(-fabsf(z)));
}
__device__ __forceinline__ uint32_t pack_h2(float a, float b) {
    __half2 h = __floats2half2_rn(a, b);
    return *reinterpret_cast<uint32_t*>(&h);
}

// A: [64 rows][STRIDE k] fp16; B: [128 n][STRIDE k] fp16. Single pass.
template<int KSTEPS, int STRIDE>
__device__ __forceinline__ void gemm_block(
    uint32_t aH, uint32_t bH,
    int m0, int nb0, int lane, float c[2][4][4])
{
    const uint32_t a_row = m0 + (lane & 15);
    const uint32_t a_k   = (lane >> 4) << 3;
    const uint32_t b_row = nb0 + ((lane >> 4) << 3) + (lane & 7);
    const uint32_t b_k   = ((lane >> 3) & 1) << 3;
    #pragma unroll
    for (int ks = 0; ks < KSTEPS; ++ks) {
        const uint32_t k0 = ks * 16;
        uint32_t ah[2][4];
        #pragma unroll
        for (int mi = 0; mi < 2; ++mi) {
            uint32_t off = ((a_row + mi * 16) * STRIDE + k0 + a_k) * 2;
            ldsm4(aH + off, ah[mi]);
        }
        #pragma unroll
        for (int ng = 0; ng < 2; ++ng) {
            uint32_t boff = ((b_row + ng * 16) * STRIDE + k0 + b_k) * 2;
            uint32_t bh[4];
            ldsm4(bH + boff, bh);
            #pragma unroll
            for (int mi = 0; mi < 2; ++mi)
                #pragma unroll
                for (int nj = 0; nj < 2; ++nj)
                    mma16816(c[mi][ng * 2 + nj], ah[mi], bh[2*nj], bh[2*nj+1]);
        }
    }
}

// stage one atom's rbf rows [32 x 64] -> fp16 into A (quad-cooperative)
__device__ __forceinline__ void stage_A(char* smem, const float* __restrict__ rbf,
                                        int atom, bool ok, int m0, int qt)
{
    const float4* rg = (const float4*)rbf + (size_t)atom * 512;
    #pragma unroll
    for (int i = 0; i < 4; ++i) {
        int idx = qt + i * 128;                // 0..511
        int row = idx >> 4, c4 = (idx & 15) << 2;
        float4 v = make_float4(0.f, 0.f, 0.f, 0.f);
        if (ok) v = rg[idx];
        uint32_t o = (uint32_t)((m0 + row) * S1 + c4) * 2;
        *(uint2*)(smem + SM_A1H + o) =
            make_uint2(pack_h2(v.x, v.y), pack_h2(v.z, v.w));
    }
}

// ---------------------------------------------------------------------------
// prep: weight transpose + fp16 images; block 0 detects neighbors dtype
// ---------------------------------------------------------------------------
__global__ void prep_weights(const float* __restrict__ w1,
                             const float* __restrict__ w2,
                             const int*   __restrict__ nb_raw) {
    if (blockIdx.x == 0) {
        __shared__ int nonzero;
        if (threadIdx.x == 0) nonzero = 0;
        __syncthreads();
        int local = 0;
        for (int i = threadIdx.x; i < 1024; i += blockDim.x) local |= nb_raw[2 * i + 1];
        if (local) atomicOr(&nonzero, 1);
        __syncthreads();
        if (threadIdx.x == 0) g_idx64_flag = (nonzero == 0) ? 1 : 0;
    }
    uint16_t* b1h = (uint16_t*)(g_wimg);
    uint16_t* b2h = (uint16_t*)(g_wimg + 128*S1*2);
    int stride = gridDim.x * blockDim.x;
    for (int idx = blockIdx.x * blockDim.x + threadIdx.x; idx < 64*128; idx += stride) {
        int r = idx >> 7, f = idx & 127;
        b1h[f * S1 + r] = __half_as_ushort(__float2half_rn(w1[idx]));
    }
    for (int idx = blockIdx.x * blockDim.x + threadIdx.x; idx < 128*128; idx += stride) {
        int g = idx >> 7, f = idx & 127;
        b2h[f * S2 + g] = __half_as_ushort(__float2half_rn(w2[idx]));
    }
}

// ---------------------------------------------------------------------------
__global__ __launch_bounds__(N_THREADS, 2)
void cfconv_mma(const float* __restrict__ x,
                const float* __restrict__ rbf,
                const void*  __restrict__ nbr,
                const float* __restrict__ b1,
                const float* __restrict__ b2,
                float* __restrict__ out,
                int n_atoms)
{
    extern __shared__ __align__(16) char smem[];
    const uint32_t sb = smem_u32(smem);
    const int t = threadIdx.x, wid = t >> 5, lane = t & 31;

    // weights image -> smem: 53248 B = 3328 float4 = 13 x 256
    {
        const float4* src = (const float4*)g_wimg;
        float4* dst = (float4*)smem;
        #pragma unroll
        for (int i = 0; i < 13; ++i) dst[t + i * N_THREADS] = src[t + i * N_THREADS];
    }
    if (t < F_DIM) {
        ((float*)(smem + SM_BS1))[t] = b1[t];
        ((float*)(smem + SM_BS2))[t] = b2[t];
    }

    const int idxsh = g_idx64_flag;
    const int* nb32 = (const int*)nbr;
    const float* bs1 = (const float*)(smem + SM_BS1);
    const float* bs2 = (const float*)(smem + SM_BS2);

    // quad = consecutive warps {4p..4p+3} -> spans all 4 SMSPs.
    const int pair = wid >> 2;          // atom slot within tile (0..1)
    const int sub  = wid & 3;           // N-quarter (0..3)
    const int bid  = pair + 1;          // named barrier id (1..2), 128 thr
    const int m0   = pair * 32;
    const int nb0  = sub * 32;
    const int qt   = sub * 32 + lane;   // thread index within quad (0..127)
    const int qr   = lane >> 2;
    const int qc   = (lane & 3) * 2;

    __syncthreads();   // weights/biases ready (only CTA-wide sync)

    // ---- prologue: stage tile 0's A rows ----
    {
        const int atom0 = blockIdx.x * ATOMS_PER_CTA + pair;
        stage_A(smem, rbf, atom0, atom0 < n_atoms, m0, qt);
    }
    bar_quad(bid);       // A(0) ready

    #pragma unroll 1
    for (int tile = 0; tile < ATOMS_PER_CTA / 2; ++tile) {
        const int abase = blockIdx.x * ATOMS_PER_CTA + tile * 2;
        const int atom  = abase + pair;
        const bool ok   = (atom < n_atoms);

        float c[2][4][4];
        #pragma unroll
        for (int mi = 0; mi < 2; ++mi)
            #pragma unroll
            for (int ng = 0; ng < 4; ++ng)
                c[mi][ng][0] = c[mi][ng][1] = c[mi][ng][2] = c[mi][ng][3] = 0.f;

        // ---- GEMM1: A@B1 (fp16) ----
        gemm_block<4, S1>(sb + SM_A1H, sb + SM_B1H, m0, nb0, lane, c);

        // ---- softplus(D1 + b1) -> H rows m0.. (own 32-col quarter) ----
        #pragma unroll
        for (int mi = 0; mi < 2; ++mi) {
            #pragma unroll
            for (int ng = 0; ng < 4; ++ng) {
                const int cc = nb0 + ng * 8 + qc;
                const int r0 = m0 + mi * 16 + qr;
                float s0 = softplus_fast(c[mi][ng][0] + bs1[cc]);
                float s1 = softplus_fast(c[mi][ng][1] + bs1[cc + 1]);
                float s2 = softplus_fast(c[mi][ng][2] + bs1[cc]);
                float s3 = softplus_fast(c[mi][ng][3] + bs1[cc + 1]);
                *(uint32_t*)(smem + SM_HH + (uint32_t)(r0 * S2 + cc) * 2)
                    = pack_h2(s0, s1);
                *(uint32_t*)(smem + SM_HH + (uint32_t)((r0 + 8) * S2 + cc) * 2)
                    = pack_h2(s2, s3);
            }
        }
        bar_quad(bid);   // #1: H ready; A fully consumed by quad's GEMM1

        // ---- stage NEXT tile's A under GEMM2 latency ----
        if (tile + 1 < ATOMS_PER_CTA / 2) {
            const int natom = abase + 2 + pair;
            stage_A(smem, rbf, natom, natom < n_atoms, m0, qt);
        }

        // neighbor indices for this atom (overlaps GEMM2 latency)
        int j = 0;
        if (ok) j = nb32[((size_t)atom * 32 + lane) << idxsh];

        #pragma unroll
        for (int mi = 0; mi < 2; ++mi)
            #pragma unroll
            for (int ng = 0; ng < 4; ++ng)
                c[mi][ng][0] = c[mi][ng][1] = c[mi][ng][2] = c[mi][ng][3] = 0.f;

        // ---- GEMM2: H@B2 (fp16) ----
        gemm_block<8, S2>(sb + SM_HH, sb + SM_B2H, m0, nb0, lane, c);
        bar_quad(bid);   // #2: GEMM2 done (H free) + A(next) staged

        // ---- epilogue: wb = half(D2+b2) in dedicated scratch; gather ----
        {
            uint32_t* wb = (uint32_t*)(smem + SM_WB + (uint32_t)pair * 8704
                                       + (uint32_t)sub * 2176);
            #pragma unroll
            for (int mi = 0; mi < 2; ++mi) {
                #pragma unroll
                for (int ng = 0; ng < 4; ++ng) {
                    const int cc = nb0 + ng * 8 + qc;     // global col
                    const int lw = ng * 4 + (lane & 3);   // half2 slot 0..15
                    const int r0 = mi * 16 + qr;          // local nb row
                    wb[r0 * 17 + lw] =
                        pack_h2(c[mi][ng][0] + bs2[cc], c[mi][ng][1] + bs2[cc + 1]);
                    wb[(r0 + 8) * 17 + lw] =
                        pack_h2(c[mi][ng][2] + bs2[cc], c[mi][ng][3] + bs2[cc + 1]);
                }
            }
            __syncwarp();

            const __half* wbh = (const __half*)wb;
            const float* x0 = x + nb0 + lane;
            float a0 = 0.f, a1 = 0.f, a2 = 0.f, a3 = 0.f;
            #pragma unroll
            for (int nb = 0; nb < 32; nb += 4) {
                const int j0 = __shfl_sync(0xffffffffu, j, nb);
                const int j1 = __shfl_sync(0xffffffffu, j, nb + 1);
                const int j2 = __shfl_sync(0xffffffffu, j, nb + 2);
                const int j3 = __shfl_sync(0xffffffffu, j, nb + 3);
                const float v0 = __ldg(x0 + (size_t)j0 * F_DIM);
                const float v1 = __ldg(x0 + (size_t)j1 * F_DIM);
                const float v2 = __ldg(x0 + (size_t)j2 * F_DIM);
                const float v3 = __ldg(x0 + (size_t)j3 * F_DIM);
                a0 = fmaf(v0, __half2float(wbh[nb * 34 + lane]), a0);
                a1 = fmaf(v1, __half2float(wbh[(nb + 1) * 34 + lane]), a1);
                a2 = fmaf(v2, __half2float(wbh[(nb + 2) * 34 + lane]), a2);
                a3 = fmaf(v3, __half2float(wbh[(nb + 3) * 34 + lane]), a3);
            }
            if (ok)
                out[(size_t)atom * F_DIM + nb0 + lane] = (a0 + a1) + (a2 + a3);
        }
        // no trailing barrier: wb is per-warp private; next softplus writes H
        // are ordered by this tile's bar #2; next GEMM1 reads A staged above.
    }
}

// ---------------------------------------------------------------------------
extern "C" void kernel_launch(void* const* d_in, const int* in_sizes, int n_in,
                              void* d_out, int out_size)
{
    const float* x    = (const float*)d_in[0];
    const float* rbf  = (const float*)d_in[1];
    const void*  nbrs = d_in[2];
    const float* w1   = (const float*)d_in[3];
    const float* b1   = (const float*)d_in[4];
    const float* w2   = (const float*)d_in[5];
    const float* b2   = (const float*)d_in[6];
    float* out = (float*)d_out;

    const int n_atoms = in_sizes[0] / F_DIM;

    cudaFuncSetAttribute(cfconv_mma,
                         cudaFuncAttributeMaxDynamicSharedMemorySize, SMEM_BYTES);

    prep_weights<<<64, 256>>>(w1, w2, (const int*)nbrs);

    const int grid = (n_atoms + ATOMS_PER_CTA - 1) / ATOMS_PER_CTA;
    cfconv_mma<<<grid, N_THREADS, SMEM_BYTES>>>(x, rbf, nbrs, b1, b2, out, n_atoms);
}

// round 13
// speedup vs baseline: 1.2657x; 1.1239x over previous
#include <cuda_runtime.h>
#include <cuda_fp16.h>
#include <cstdint>

// ===========================================================================
// CFConv via mma.sync (HMMA fp16 m16n8k16, fp32 accum), single-pass fp16.
// 256 thr / CTA = 8 warps = 4 atom-PAIRS (2 warps per atom, N=64 per warp):
// halves A-fragment LDSM redundancy vs quads (-25% GEMM shared traffic).
// 3 named barriers per tile (bar#3 protects wb-in-H from next softplus);
// next-tile A staged under GEMM2; L1-cached __ldg x-gather.
// ===========================================================================

#define N_THREADS 256
#define ATOMS_PER_CTA 8
#define F_DIM 128

// padded element strides (odd multiples of 8 halves -> conflict-free ldmatrix)
#define S1 72    // K=64 tiles
#define S2 136   // K=128 tiles

// ---- smem byte offsets ----
#define SM_B1H 0                         // 128*72*2  = 18432
#define SM_B2H (SM_B1H + 128*S1*2)       // 128*136*2 = 34816 -> ends 53248
#define SM_A1H (SM_B2H + 128*S2*2)       // 128*72*2  = 18432 -> ends 71680
#define SM_HH  (SM_A1H + 128*S1*2)       // 128*136*2 = 34816 -> ends 106496
#define SM_BS1 (SM_HH  + 128*S2*2)       // 512
#define SM_BS2 (SM_BS1 + 512)
#define SMEM_BYTES (SM_BS2 + 512)        // 107520 (2 CTAs: 215040 <= 227328)

#define WIMG_BYTES (128*S1*2 + 128*S2*2) // 53248
__device__ __align__(16) unsigned char g_wimg[WIMG_BYTES];
__device__ int g_idx64_flag;

// ---------------------------------------------------------------------------
__device__ __forceinline__ uint32_t smem_u32(const void* p) {
    uint32_t a;
    asm("{ .reg .u64 t; cvta.to.shared.u64 t, %1; cvt.u32.u64 %0, t; }" : "=r"(a) : "l"(p));
    return a;
}
__device__ __forceinline__ void bar_pair(int id) {
    asm volatile("bar.sync %0, %1;" :: "r"(id), "r"(64) : "memory");
}
__device__ __forceinline__ void ldsm4(uint32_t addr, uint32_t r[4]) {
    asm volatile("ldmatrix.sync.aligned.m8n8.x4.shared.b16 {%0,%1,%2,%3}, [%4];"
        : "=r"(r[0]), "=r"(r[1]), "=r"(r[2]), "=r"(r[3]) : "r"(addr));
}
__device__ __forceinline__ void mma16816(float c[4], const uint32_t a[4],
                                         uint32_t b0, uint32_t b1) {
    asm volatile("mma.sync.aligned.m16n8k16.row.col.f32.f16.f16.f32 "
        "{%0,%1,%2,%3}, {%4,%5,%6,%7}, {%8,%9}, {%0,%1,%2,%3};"
        : "+f"(c[0]), "+f"(c[1]), "+f"(c[2]), "+f"(c[3])
        : "r"(a[0]), "r"(a[1]), "r"(a[2]), "r"(a[3]), "r"(b0), "r"(b1));
}
__device__ __forceinline__ float softplus_fast(float z) {
    return fmaxf(z, 0.0f) + __logf(1.0f + __expf(-fabsf(z)));
}
__device__ __forceinline__ uint32_t pack_h2(float a, float b) {
    __half2 h = __floats2half2_rn(a, b);
    return *reinterpret_cast<uint32_t*>(&h);
}

// A: [128 rows][STRIDE k] fp16; B: [128 n][STRIDE k] fp16. Single pass.
// Warp computes C[m0..+31][nb0..+63]: 4 N-groups of 16.
template<int KSTEPS, int STRIDE>
__device__ __forceinline__ void gemm_block(
    uint32_t aH, uint32_t bH,
    int m0, int nb0, int lane, float c[2][8][4])
{
    const uint32_t a_row = m0 + (lane & 15);
    const uint32_t a_k   = (lane >> 4) << 3;
    const uint32_t b_row = nb0 + ((lane >> 4) << 3) + (lane & 7);
    const uint32_t b_k   = ((lane >> 3) & 1) << 3;
    #pragma unroll
    for (int ks = 0; ks < KSTEPS; ++ks) {
        const uint32_t k0 = ks * 16;
        uint32_t ah[2][4];
        #pragma unroll
        for (int mi = 0; mi < 2; ++mi) {
            uint32_t off = ((a_row + mi * 16) * STRIDE + k0 + a_k) * 2;
            ldsm4(aH + off, ah[mi]);
        }
        #pragma unroll
        for (int ng = 0; ng < 4; ++ng) {
            uint32_t boff = ((b_row + ng * 16) * STRIDE + k0 + b_k) * 2;
            uint32_t bh[4];
            ldsm4(bH + boff, bh);
            #pragma unroll
            for (int mi = 0; mi < 2; ++mi)
                #pragma unroll
                for (int nj = 0; nj < 2; ++nj)
                    mma16816(c[mi][ng * 2 + nj], ah[mi], bh[2*nj], bh[2*nj+1]);
        }
    }
}

// stage one atom's rbf rows [32 x 64] -> fp16 into A (pair-cooperative, 64 thr)
__device__ __forceinline__ void stage_A(char* smem, const float* __restrict__ rbf,
                                        int atom, bool ok, int m0, int pt)
{
    const float4* rg = (const float4*)rbf + (size_t)atom * 512;
    #pragma unroll
    for (int i = 0; i < 8; ++i) {
        int idx = pt + i * 64;                 // 0..511
        int row = idx >> 4, c4 = (idx & 15) << 2;
        float4 v = make_float4(0.f, 0.f, 0.f, 0.f);
        if (ok) v = rg[idx];
        uint32_t o = (uint32_t)((m0 + row) * S1 + c4) * 2;
        *(uint2*)(smem + SM_A1H + o) =
            make_uint2(pack_h2(v.x, v.y), pack_h2(v.z, v.w));
    }
}

// ---------------------------------------------------------------------------
// prep: weight transpose + fp16 images; block 0 detects neighbors dtype
// ---------------------------------------------------------------------------
__global__ void prep_weights(const float* __restrict__ w1,
                             const float* __restrict__ w2,
                             const int*   __restrict__ nb_raw) {
    if (blockIdx.x == 0) {
        __shared__ int nonzero;
        if (threadIdx.x == 0) nonzero = 0;
        __syncthreads();
        int local = 0;
        for (int i = threadIdx.x; i < 1024; i += blockDim.x) local |= nb_raw[2 * i + 1];
        if (local) atomicOr(&nonzero, 1);
        __syncthreads();
        if (threadIdx.x == 0) g_idx64_flag = (nonzero == 0) ? 1 : 0;
    }
    uint16_t* b1h = (uint16_t*)(g_wimg);
    uint16_t* b2h = (uint16_t*)(g_wimg + 128*S1*2);
    int stride = gridDim.x * blockDim.x;
    for (int idx = blockIdx.x * blockDim.x + threadIdx.x; idx < 64*128; idx += stride) {
        int r = idx >> 7, f = idx & 127;
        b1h[f * S1 + r] = __half_as_ushort(__float2half_rn(w1[idx]));
    }
    for (int idx = blockIdx.x * blockDim.x + threadIdx.x; idx < 128*128; idx += stride) {
        int g = idx >> 7, f = idx & 127;
        b2h[f * S2 + g] = __half_as_ushort(__float2half_rn(w2[idx]));
    }
}

// ---------------------------------------------------------------------------
__global__ __launch_bounds__(N_THREADS, 2)
void cfconv_mma(const float* __restrict__ x,
                const float* __restrict__ rbf,
                const void*  __restrict__ nbr,
                const float* __restrict__ b1,
                const float* __restrict__ b2,
                float* __restrict__ out,
                int n_atoms)
{
    extern __shared__ __align__(16) char smem[];
    const uint32_t sb = smem_u32(smem);
    const int t = threadIdx.x, wid = t >> 5, lane = t & 31;

    // weights image -> smem: 53248 B = 3328 float4 = 13 x 256
    {
        const float4* src = (const float4*)g_wimg;
        float4* dst = (float4*)smem;
        #pragma unroll
        for (int i = 0; i < 13; ++i) dst[t + i * N_THREADS] = src[t + i * N_THREADS];
    }
    if (t < F_DIM) {
        ((float*)(smem + SM_BS1))[t] = b1[t];
        ((float*)(smem + SM_BS2))[t] = b2[t];
    }

    const int idxsh = g_idx64_flag;
    const int* nb32 = (const int*)nbr;
    const float* bs1 = (const float*)(smem + SM_BS1);
    const float* bs2 = (const float*)(smem + SM_BS2);

    // pair = consecutive warps {2p, 2p+1}; 4 pairs cover all SMSPs.
    const int pr  = wid >> 1;           // atom slot within tile (0..3)
    const int sub = wid & 1;            // N-half (0..1)
    const int bid = pr + 1;             // named barrier id (1..4), 64 thr
    const int m0  = pr * 32;
    const int nb0 = sub * 64;
    const int pt  = sub * 32 + lane;    // thread index within pair (0..63)
    const int qr  = lane >> 2;
    const int qc  = (lane & 3) * 2;

    __syncthreads();   // weights/biases ready (only CTA-wide sync)

    // ---- prologue: stage tile 0's A rows ----
    {
        const int atom0 = blockIdx.x * ATOMS_PER_CTA + pr;
        stage_A(smem, rbf, atom0, atom0 < n_atoms, m0, pt);
    }
    bar_pair(bid);       // A(0) ready

    #pragma unroll 1
    for (int tile = 0; tile < ATOMS_PER_CTA / 4; ++tile) {
        const int abase = blockIdx.x * ATOMS_PER_CTA + tile * 4;
        const int atom  = abase + pr;
        const bool ok   = (atom < n_atoms);

        float c[2][8][4];
        #pragma unroll
        for (int mi = 0; mi < 2; ++mi)
            #pragma unroll
            for (int ng = 0; ng < 8; ++ng)
                c[mi][ng][0] = c[mi][ng][1] = c[mi][ng][2] = c[mi][ng][3] = 0.f;

        // ---- GEMM1: A@B1 (fp16) ----
        gemm_block<4, S1>(sb + SM_A1H, sb + SM_B1H, m0, nb0, lane, c);

        // ---- softplus(D1 + b1) -> H rows m0.. (own 64-col half) ----
        #pragma unroll
        for (int mi = 0; mi < 2; ++mi) {
            #pragma unroll
            for (int ng = 0; ng < 8; ++ng) {
                const int cc = nb0 + ng * 8 + qc;
                const int r0 = m0 + mi * 16 + qr;
                float s0 = softplus_fast(c[mi][ng][0] + bs1[cc]);
                float s1 = softplus_fast(c[mi][ng][1] + bs1[cc + 1]);
                float s2 = softplus_fast(c[mi][ng][2] + bs1[cc]);
                float s3 = softplus_fast(c[mi][ng][3] + bs1[cc + 1]);
                *(uint32_t*)(smem + SM_HH + (uint32_t)(r0 * S2 + cc) * 2)
                    = pack_h2(s0, s1);
                *(uint32_t*)(smem + SM_HH + (uint32_t)((r0 + 8) * S2 + cc) * 2)
                    = pack_h2(s2, s3);
            }
        }
        bar_pair(bid);   // #1: H rows m0.. ready; A consumed by pair's GEMM1

        // ---- stage NEXT tile's A under GEMM2 latency ----
        if (tile + 1 < ATOMS_PER_CTA / 4) {
            const int natom = abase + 4 + pr;
            stage_A(smem, rbf, natom, natom < n_atoms, m0, pt);
        }

        // neighbor indices for this atom (overlaps GEMM2 latency)
        int j = 0;
        if (ok) j = nb32[((size_t)atom * 32 + lane) << idxsh];

        #pragma unroll
        for (int mi = 0; mi < 2; ++mi)
            #pragma unroll
            for (int ng = 0; ng < 8; ++ng)
                c[mi][ng][0] = c[mi][ng][1] = c[mi][ng][2] = c[mi][ng][3] = 0.f;

        // ---- GEMM2: H@B2 (fp16) ----
        gemm_block<8, S2>(sb + SM_HH, sb + SM_B2H, m0, nb0, lane, c);
        bar_pair(bid);   // #2: pair GEMM2 done (H rows free) + A(next) staged

        // ---- epilogue: wb = half(D2+b2) in atom's dead H rows; gather ----
        {
            // atom's H rows = 8704 B; per-warp fp16 scratch 32x68 halves=4352 B
            uint32_t* wb = (uint32_t*)(smem + SM_HH + (uint32_t)m0 * S2 * 2
                                       + (uint32_t)sub * 4352);
            #pragma unroll
            for (int mi = 0; mi < 2; ++mi) {
                #pragma unroll
                for (int ng = 0; ng < 8; ++ng) {
                    const int cc = nb0 + ng * 8 + qc;     // global col
                    const int lw = ng * 4 + (lane & 3);   // half2 slot 0..31
                    const int r0 = mi * 16 + qr;          // local nb row
                    wb[r0 * 34 + lw] =
                        pack_h2(c[mi][ng][0] + bs2[cc], c[mi][ng][1] + bs2[cc + 1]);
                    wb[(r0 + 8) * 34 + lw] =
                        pack_h2(c[mi][ng][2] + bs2[cc], c[mi][ng][3] + bs2[cc + 1]);
                }
            }
            __syncwarp();

            const __half* wbh = (const __half*)wb;
            const float* x0 = x + nb0 + lane;
            float a0 = 0.f, a1 = 0.f, a2 = 0.f, a3 = 0.f;
            #pragma unroll
            for (int nb = 0; nb < 32; nb += 2) {
                const int j0 = __shfl_sync(0xffffffffu, j, nb);
                const int j1 = __shfl_sync(0xffffffffu, j, nb + 1);
                const float* r0p = x0 + (size_t)j0 * F_DIM;
                const float* r1p = x0 + (size_t)j1 * F_DIM;
                a0 = fmaf(__ldg(r0p),      __half2float(wbh[nb * 68 + lane]), a0);
                a1 = fmaf(__ldg(r0p + 32), __half2float(wbh[nb * 68 + 32 + lane]), a1);
                a2 = fmaf(__ldg(r1p),      __half2float(wbh[(nb+1) * 68 + lane]), a2);
                a3 = fmaf(__ldg(r1p + 32), __half2float(wbh[(nb+1) * 68 + 32 + lane]), a3);
            }
            if (ok) {
                out[(size_t)atom * F_DIM + nb0 + lane]      = a0 + a2;
                out[(size_t)atom * F_DIM + nb0 + 32 + lane] = a1 + a3;
            }
        }
        bar_pair(bid);   // #3: both epilogues done -> H rows safe for next
                         //     tile's softplus writes (wb lives in H rows)
    }
}

// ---------------------------------------------------------------------------
extern "C" void kernel_launch(void* const* d_in, const int* in_sizes, int n_in,
                              void* d_out, int out_size)
{
    const float* x    = (const float*)d_in[0];
    const float* rbf  = (const float*)d_in[1];
    const void*  nbrs = d_in[2];
    const float* w1   = (const float*)d_in[3];
    const float* b1   = (const float*)d_in[4];
    const float* w2   = (const float*)d_in[5];
    const float* b2   = (const float*)d_in[6];
    float* out = (float*)d_out;

    const int n_atoms = in_sizes[0] / F_DIM;

    cudaFuncSetAttribute(cfconv_mma,
                         cudaFuncAttributeMaxDynamicSharedMemorySize, SMEM_BYTES);

    prep_weights<<<64, 256>>>(w1, w2, (const int*)nbrs);

    const int grid = (n_atoms + ATOMS_PER_CTA - 1) / ATOMS_PER_CTA;
    cfconv_mma<<<grid, N_THREADS, SMEM_BYTES>>>(x, rbf, nbrs, b1, b2, out, n_atoms);
}

// round 14
// speedup vs baseline: 1.2700x; 1.0034x over previous
#include <cuda_runtime.h>
#include <cuda_fp16.h>
#include <cstdint>

// ===========================================================================
// CFConv via mma.sync (HMMA fp16 m16n8k16, fp32 accum), single-pass fp16.
// 256 thr / CTA = 8 warps = 4 atom-PAIRS (2 warps per atom, N=64 per warp).
// R14: (1) softplus packs double as register-resident A2 fragments for the
//      warp's own 64 k-cols (C1->A2 layout identity); G2 loads only the
//      partner half from smem. (2) epilogue = in-register x*W multiply +
//      shfl.xor reduction over nb rows (no wb smem round-trip, fp32 W).
// 2 named barriers per tile; next-tile A staged under GEMM2.
// ===========================================================================

#define N_THREADS 256
#define ATOMS_PER_CTA 8
#define F_DIM 128

// padded element strides (odd multiples of 8 halves -> conflict-free ldmatrix)
#define S1 72    // K=64 tiles
#define S2 136   // K=128 tiles

// ---- smem byte offsets ----
#define SM_B1H 0                         // 128*72*2  = 18432
#define SM_B2H (SM_B1H + 128*S1*2)       // 128*136*2 = 34816 -> ends 53248
#define SM_A1H (SM_B2H + 128*S2*2)       // 128*72*2  = 18432 -> ends 71680
#define SM_HH  (SM_A1H + 128*S1*2)       // 128*136*2 = 34816 -> ends 106496
#define SM_BS1 (SM_HH  + 128*S2*2)       // 512
#define SM_BS2 (SM_BS1 + 512)
#define SMEM_BYTES (SM_BS2 + 512)        // 107520 (2 CTAs: 215040 <= 227328)

#define WIMG_BYTES (128*S1*2 + 128*S2*2) // 53248
__device__ __align__(16) unsigned char g_wimg[WIMG_BYTES];
__device__ int g_idx64_flag;

// ---------------------------------------------------------------------------
__device__ __forceinline__ uint32_t smem_u32(const void* p) {
    uint32_t a;
    asm("{ .reg .u64 t; cvta.to.shared.u64 t, %1; cvt.u32.u64 %0, t; }" : "=r"(a) : "l"(p));
    return a;
}
__device__ __forceinline__ void bar_pair(int id) {
    asm volatile("bar.sync %0, %1;" :: "r"(id), "r"(64) : "memory");
}
__device__ __forceinline__ void ldsm4(uint32_t addr, uint32_t r[4]) {
    asm volatile("ldmatrix.sync.aligned.m8n8.x4.shared.b16 {%0,%1,%2,%3}, [%4];"
        : "=r"(r[0]), "=r"(r[1]), "=r"(r[2]), "=r"(r[3]) : "r"(addr));
}
__device__ __forceinline__ void mma16816(float c[4], const uint32_t a[4],
                                         uint32_t b0, uint32_t b1) {
    asm volatile("mma.sync.aligned.m16n8k16.row.col.f32.f16.f16.f32 "
        "{%0,%1,%2,%3}, {%4,%5,%6,%7}, {%8,%9}, {%0,%1,%2,%3};"
        : "+f"(c[0]), "+f"(c[1]), "+f"(c[2]), "+f"(c[3])
        : "r"(a[0]), "r"(a[1]), "r"(a[2]), "r"(a[3]), "r"(b0), "r"(b1));
}
__device__ __forceinline__ float softplus_fast(float z) {
    return fmaxf(z, 0.0f) + __logf(1.0f + __expf(-fabsf(z)));
}
__device__ __forceinline__ uint32_t pack_h2(float a, float b) {
    __half2 h = __floats2half2_rn(a, b);
    return *reinterpret_cast<uint32_t*>(&h);
}

// A: [128 rows][STRIDE k] fp16; B: [128 n][STRIDE k] fp16. Single pass.
// Warp computes C[m0..+31][nb0..+63]: 4 N-groups of 16. (used for GEMM1)
template<int KSTEPS, int STRIDE>
__device__ __forceinline__ void gemm_block(
    uint32_t aH, uint32_t bH,
    int m0, int nb0, int lane, float c[2][8][4])
{
    const uint32_t a_row = m0 + (lane & 15);
    const uint32_t a_k   = (lane >> 4) << 3;
    const uint32_t b_row = nb0 + ((lane >> 4) << 3) + (lane & 7);
    const uint32_t b_k   = ((lane >> 3) & 1) << 3;
    #pragma unroll
    for (int ks = 0; ks < KSTEPS; ++ks) {
        const uint32_t k0 = ks * 16;
        uint32_t ah[2][4];
        #pragma unroll
        for (int mi = 0; mi < 2; ++mi) {
            uint32_t off = ((a_row + mi * 16) * STRIDE + k0 + a_k) * 2;
            ldsm4(aH + off, ah[mi]);
        }
        #pragma unroll
        for (int ng = 0; ng < 4; ++ng) {
            uint32_t boff = ((b_row + ng * 16) * STRIDE + k0 + b_k) * 2;
            uint32_t bh[4];
            ldsm4(bH + boff, bh);
            #pragma unroll
            for (int mi = 0; mi < 2; ++mi)
                #pragma unroll
                for (int nj = 0; nj < 2; ++nj)
                    mma16816(c[mi][ng * 2 + nj], ah[mi], bh[2*nj], bh[2*nj+1]);
        }
    }
}

// stage one atom's rbf rows [32 x 64] -> fp16 into A (pair-cooperative, 64 thr)
__device__ __forceinline__ void stage_A(char* smem, const float* __restrict__ rbf,
                                        int atom, bool ok, int m0, int pt)
{
    const float4* rg = (const float4*)rbf + (size_t)atom * 512;
    #pragma unroll
    for (int i = 0; i < 8; ++i) {
        int idx = pt + i * 64;                 // 0..511
        int row = idx >> 4, c4 = (idx & 15) << 2;
        float4 v = make_float4(0.f, 0.f, 0.f, 0.f);
        if (ok) v = rg[idx];
        uint32_t o = (uint32_t)((m0 + row) * S1 + c4) * 2;
        *(uint2*)(smem + SM_A1H + o) =
            make_uint2(pack_h2(v.x, v.y), pack_h2(v.z, v.w));
    }
}

// ---------------------------------------------------------------------------
// prep: weight transpose + fp16 images; block 0 detects neighbors dtype
// ---------------------------------------------------------------------------
__global__ void prep_weights(const float* __restrict__ w1,
                             const float* __restrict__ w2,
                             const int*   __restrict__ nb_raw) {
    if (blockIdx.x == 0) {
        __shared__ int nonzero;
        if (threadIdx.x == 0) nonzero = 0;
        __syncthreads();
        int local = 0;
        for (int i = threadIdx.x; i < 1024; i += blockDim.x) local |= nb_raw[2 * i + 1];
        if (local) atomicOr(&nonzero, 1);
        __syncthreads();
        if (threadIdx.x == 0) g_idx64_flag = (nonzero == 0) ? 1 : 0;
    }
    uint16_t* b1h = (uint16_t*)(g_wimg);
    uint16_t* b2h = (uint16_t*)(g_wimg + 128*S1*2);
    int stride = gridDim.x * blockDim.x;
    for (int idx = blockIdx.x * blockDim.x + threadIdx.x; idx < 64*128; idx += stride) {
        int r = idx >> 7, f = idx & 127;
        b1h[f * S1 + r] = __half_as_ushort(__float2half_rn(w1[idx]));
    }
    for (int idx = blockIdx.x * blockDim.x + threadIdx.x; idx < 128*128; idx += stride) {
        int g = idx >> 7, f = idx & 127;
        b2h[f * S2 + g] = __half_as_ushort(__float2half_rn(w2[idx]));
    }
}

// ---------------------------------------------------------------------------
__global__ __launch_bounds__(N_THREADS, 2)
void cfconv_mma(const float* __restrict__ x,
                const float* __restrict__ rbf,
                const void*  __restrict__ nbr,
                const float* __restrict__ b1,
                const float* __restrict__ b2,
                float* __restrict__ out,
                int n_atoms)
{
    extern __shared__ __align__(16) char smem[];
    const uint32_t sb = smem_u32(smem);
    const int t = threadIdx.x, wid = t >> 5, lane = t & 31;

    // weights image -> smem: 53248 B = 3328 float4 = 13 x 256
    {
        const float4* src = (const float4*)g_wimg;
        float4* dst = (float4*)smem;
        #pragma unroll
        for (int i = 0; i < 13; ++i) dst[t + i * N_THREADS] = src[t + i * N_THREADS];
    }
    if (t < F_DIM) {
        ((float*)(smem + SM_BS1))[t] = b1[t];
        ((float*)(smem + SM_BS2))[t] = b2[t];
    }

    const int idxsh = g_idx64_flag;
    const int* nb32 = (const int*)nbr;
    const float* bs1 = (const float*)(smem + SM_BS1);
    const float* bs2 = (const float*)(smem + SM_BS2);

    // pair = consecutive warps {2p, 2p+1}; 4 pairs cover all SMSPs.
    const int pr  = wid >> 1;           // atom slot within tile (0..3)
    const int sub = wid & 1;            // N-half (0..1)
    const int bid = pr + 1;             // named barrier id (1..4), 64 thr
    const int m0  = pr * 32;
    const int nb0 = sub * 64;
    const int pt  = sub * 32 + lane;    // thread index within pair (0..63)
    const int qr  = lane >> 2;
    const int qc  = (lane & 3) * 2;

    __syncthreads();   // weights/biases ready (only CTA-wide sync)

    // ---- prologue: stage tile 0's A rows ----
    {
        const int atom0 = blockIdx.x * ATOMS_PER_CTA + pr;
        stage_A(smem, rbf, atom0, atom0 < n_atoms, m0, pt);
    }
    bar_pair(bid);       // A(0) ready

    #pragma unroll 1
    for (int tile = 0; tile < ATOMS_PER_CTA / 4; ++tile) {
        const int abase = blockIdx.x * ATOMS_PER_CTA + tile * 4;
        const int atom  = abase + pr;
        const bool ok   = (atom < n_atoms);

        float c[2][8][4];
        #pragma unroll
        for (int mi = 0; mi < 2; ++mi)
            #pragma unroll
            for (int ng = 0; ng < 8; ++ng)
                c[mi][ng][0] = c[mi][ng][1] = c[mi][ng][2] = c[mi][ng][3] = 0.f;

        // ---- GEMM1: A@B1 (fp16) ----
        gemm_block<4, S1>(sb + SM_A1H, sb + SM_B1H, m0, nb0, lane, c);

        // ---- softplus(D1+b1): pack -> regs (A2 own-half frags) + smem ----
        uint32_t hA[2][8], hB[2][8];   // row qr / row qr+8 packs
        #pragma unroll
        for (int mi = 0; mi < 2; ++mi) {
            #pragma unroll
            for (int ng = 0; ng < 8; ++ng) {
                const int cc = nb0 + ng * 8 + qc;
                const int r0 = m0 + mi * 16 + qr;
                float s0 = softplus_fast(c[mi][ng][0] + bs1[cc]);
                float s1 = softplus_fast(c[mi][ng][1] + bs1[cc + 1]);
                float s2 = softplus_fast(c[mi][ng][2] + bs1[cc]);
                float s3 = softplus_fast(c[mi][ng][3] + bs1[cc + 1]);
                hA[mi][ng] = pack_h2(s0, s1);
                hB[mi][ng] = pack_h2(s2, s3);
                *(uint32_t*)(smem + SM_HH + (uint32_t)(r0 * S2 + cc) * 2)
                    = hA[mi][ng];
                *(uint32_t*)(smem + SM_HH + (uint32_t)((r0 + 8) * S2 + cc) * 2)
                    = hB[mi][ng];
            }
        }
        bar_pair(bid);   // #1: H halves ready; A consumed by pair's GEMM1

        // ---- stage NEXT tile's A under GEMM2 latency ----
        if (tile + 1 < ATOMS_PER_CTA / 4) {
            const int natom = abase + 4 + pr;
            stage_A(smem, rbf, natom, natom < n_atoms, m0, pt);
        }

        // neighbor indices for this atom (overlaps GEMM2 latency)
        int j = 0;
        if (ok) j = nb32[((size_t)atom * 32 + lane) << idxsh];

        #pragma unroll
        for (int mi = 0; mi < 2; ++mi)
            #pragma unroll
            for (int ng = 0; ng < 8; ++ng)
                c[mi][ng][0] = c[mi][ng][1] = c[mi][ng][2] = c[mi][ng][3] = 0.f;

        // ---- GEMM2: H@B2 (fp16). Own 4 k-tiles from regs, partner 4 via ldsm.
        {
            const uint32_t b_row = nb0 + ((lane >> 4) << 3) + (lane & 7);
            const uint32_t b_k   = ((lane >> 3) & 1) << 3;
            // own-half k-tiles (k cols nb0..nb0+63): A frags = softplus packs
            #pragma unroll
            for (int kl = 0; kl < 4; ++kl) {
                uint32_t ah0[4] = { hA[0][2*kl], hB[0][2*kl],
                                    hA[0][2*kl+1], hB[0][2*kl+1] };
                uint32_t ah1[4] = { hA[1][2*kl], hB[1][2*kl],
                                    hA[1][2*kl+1], hB[1][2*kl+1] };
                const uint32_t k0 = nb0 + kl * 16;
                #pragma unroll
                for (int ng = 0; ng < 4; ++ng) {
                    uint32_t boff = ((b_row + ng * 16) * S2 + k0 + b_k) * 2;
                    uint32_t bh[4];
                    ldsm4(sb + SM_B2H + boff, bh);
                    #pragma unroll
                    for (int nj = 0; nj < 2; ++nj) {
                        mma16816(c[0][ng * 2 + nj], ah0, bh[2*nj], bh[2*nj+1]);
                        mma16816(c[1][ng * 2 + nj], ah1, bh[2*nj], bh[2*nj+1]);
                    }
                }
            }
            // partner-half k-tiles (k cols nb0^64 ..): A via ldsm from H
            const uint32_t a_row = m0 + (lane & 15);
            const uint32_t a_k   = (lane >> 4) << 3;
            const int pb = nb0 ^ 64;
            #pragma unroll
            for (int kl = 0; kl < 4; ++kl) {
                const uint32_t k0 = pb + kl * 16;
                uint32_t ah[2][4];
                #pragma unroll
                for (int mi = 0; mi < 2; ++mi) {
                    uint32_t off = ((a_row + mi * 16) * S2 + k0 + a_k) * 2;
                    ldsm4(sb + SM_HH + off, ah[mi]);
                }
                #pragma unroll
                for (int ng = 0; ng < 4; ++ng) {
                    uint32_t boff = ((b_row + ng * 16) * S2 + k0 + b_k) * 2;
                    uint32_t bh[4];
                    ldsm4(sb + SM_B2H + boff, bh);
                    #pragma unroll
                    for (int mi = 0; mi < 2; ++mi)
                        #pragma unroll
                        for (int nj = 0; nj < 2; ++nj)
                            mma16816(c[mi][ng * 2 + nj], ah[mi],
                                     bh[2*nj], bh[2*nj+1]);
                }
            }
        }
        bar_pair(bid);   // #2: pair GEMM2 done (H free) + A(next) staged

        // ---- epilogue: in-register x*(D2+b2), shfl.xor reduce over nb ----
        {
            const int j0 = __shfl_sync(0xffffffffu, j, qr);
            const int j1 = __shfl_sync(0xffffffffu, j, qr + 8);
            const int j2 = __shfl_sync(0xffffffffu, j, qr + 16);
            const int j3 = __shfl_sync(0xffffffffu, j, qr + 24);
            const float* xr0 = x + (size_t)j0 * F_DIM;
            const float* xr1 = x + (size_t)j1 * F_DIM;
            const float* xr2 = x + (size_t)j2 * F_DIM;
            const float* xr3 = x + (size_t)j3 * F_DIM;
            float* orow = out + (size_t)atom * F_DIM;
            #pragma unroll
            for (int ng = 0; ng < 8; ++ng) {
                const int cc = nb0 + ng * 8 + qc;
                const float2 bv  = *(const float2*)&bs2[cc];
                const float2 x0v = *(const float2*)(xr0 + cc);
                const float2 x1v = *(const float2*)(xr1 + cc);
                const float2 x2v = *(const float2*)(xr2 + cc);
                const float2 x3v = *(const float2*)(xr3 + cc);
                // rows: qr (c[0][..][0,1]), qr+8 (c[0][..][2,3]),
                //       qr+16 (c[1][..][0,1]), qr+24 (c[1][..][2,3])
                float s0 = (c[0][ng][0] + bv.x) * x0v.x
                         + (c[0][ng][2] + bv.x) * x1v.x
                         + (c[1][ng][0] + bv.x) * x2v.x
                         + (c[1][ng][2] + bv.x) * x3v.x;
                float s1 = (c[0][ng][1] + bv.y) * x0v.y
                         + (c[0][ng][3] + bv.y) * x1v.y
                         + (c[1][ng][1] + bv.y) * x2v.y
                         + (c[1][ng][3] + bv.y) * x3v.y;
                s0 += __shfl_xor_sync(0xffffffffu, s0, 4);
                s1 += __shfl_xor_sync(0xffffffffu, s1, 4);
                s0 += __shfl_xor_sync(0xffffffffu, s0, 8);
                s1 += __shfl_xor_sync(0xffffffffu, s1, 8);
                s0 += __shfl_xor_sync(0xffffffffu, s0, 16);
                s1 += __shfl_xor_sync(0xffffffffu, s1, 16);
                if (ok && qr == 0)
                    *(float2*)(orow + cc) = make_float2(s0, s1);
            }
        }
        // no bar#3 needed: epilogue touches no shared scratch; H(next) writes
        // are ordered after bar#2 via each warp's own program order.
    }
}

// ---------------------------------------------------------------------------
extern "C" void kernel_launch(void* const* d_in, const int* in_sizes, int n_in,
                              void* d_out, int out_size)
{
    const float* x    = (const float*)d_in[0];
    const float* rbf  = (const float*)d_in[1];
    const void*  nbrs = d_in[2];
    const float* w1   = (const float*)d_in[3];
    const float* b1   = (const float*)d_in[4];
    const float* w2   = (const float*)d_in[5];
    const float* b2   = (const float*)d_in[6];
    float* out = (float*)d_out;

    const int n_atoms = in_sizes[0] / F_DIM;

    cudaFuncSetAttribute(cfconv_mma,
                         cudaFuncAttributeMaxDynamicSharedMemorySize, SMEM_BYTES);

    prep_weights<<<64, 256>>>(w1, w2, (const int*)nbrs);

    const int grid = (n_atoms + ATOMS_PER_CTA - 1) / ATOMS_PER_CTA;
    cfconv_mma<<<grid, N_THREADS, SMEM_BYTES>>>(x, rbf, nbrs, b1, b2, out, n_atoms);
}